// round 1
// baseline (speedup 1.0000x reference)
#include <cuda_runtime.h>
#include <math.h>

#define BB 8192
#define DD 256

// Scratch (device globals — no allocations allowed in kernel_launch)
__device__ float    g_f[BB * DD];                 // normalized feats
__device__ float    g_sq[BB];                     // per-row sum of squares of normalized feats
__device__ float    g_dist[(size_t)BB * BB];      // full distance matrix (256 MiB)
__device__ unsigned g_minpos[BB];                 // float bits, min over mined positives
__device__ unsigned g_maxneg[BB];                 // float bits, max over negatives

// ---------------------------------------------------------------------------
// Kernel 0: init accumulators
// ---------------------------------------------------------------------------
__global__ void init_kernel(float* out) {
    int t = blockIdx.x * blockDim.x + threadIdx.x;
    if (t < BB) {
        g_minpos[t] = 0x7F800000u;   // +inf
        g_maxneg[t] = 0u;            // 0.0f (all dists >= 0; rows w/o negs are invalid anyway)
    }
    if (t == 0) out[0] = 0.0f;
}

// ---------------------------------------------------------------------------
// Kernel 1: normalize rows; also compute sq = sum(fn*fn) per row
// one block (256 threads) per row
// ---------------------------------------------------------------------------
__global__ __launch_bounds__(256) void norm_kernel(const float* __restrict__ feats) {
    int row = blockIdx.x;
    int tid = threadIdx.x;
    float v = feats[row * DD + tid];

    float s = v * v;
    #pragma unroll
    for (int o = 16; o > 0; o >>= 1) s += __shfl_xor_sync(0xffffffffu, s, o);

    __shared__ float sw[8];
    if ((tid & 31) == 0) sw[tid >> 5] = s;
    __syncthreads();
    float tot = sw[0] + sw[1] + sw[2] + sw[3] + sw[4] + sw[5] + sw[6] + sw[7];

    float inv = 1.0f / (sqrtf(tot) + 1e-12f);
    float fn = v * inv;
    g_f[row * DD + tid] = fn;

    float s2 = fn * fn;
    #pragma unroll
    for (int o = 16; o > 0; o >>= 1) s2 += __shfl_xor_sync(0xffffffffu, s2, o);
    __syncthreads();
    if ((tid & 31) == 0) sw[tid >> 5] = s2;
    __syncthreads();
    if (tid == 0)
        g_sq[row] = sw[0] + sw[1] + sw[2] + sw[3] + sw[4] + sw[5] + sw[6] + sw[7];
}

// ---------------------------------------------------------------------------
// Kernel 2: tiled fp32 GEMM (dot products) + dist epilogue + pass-1 mining.
// 128x128 tile per 256-thread block, 8x8 per thread. Only bi <= bj computed;
// transposed tile is mirrored into g_dist. Per-row/col min/max done in shared
// memory, then folded into global via ~512 atomics per block.
// ---------------------------------------------------------------------------
__global__ __launch_bounds__(256) void gemm_kernel(const int* __restrict__ labels) {
    int bj = blockIdx.x;   // column tile
    int bi = blockIdx.y;   // row tile
    if (bi > bj) return;

    __shared__ float As[32][128];
    __shared__ float Bs[32][128];

    int tid = threadIdx.x;
    int tx = tid & 15;      // 0..15 -> 8 cols each
    int ty = tid >> 4;      // 0..15 -> 8 rows each

    float acc[8][8];
    #pragma unroll
    for (int i = 0; i < 8; i++)
        #pragma unroll
        for (int j = 0; j < 8; j++) acc[i][j] = 0.0f;

    int lm = tid >> 1;             // row within tile loaded by this thread (0..127)
    int lk = (tid & 1) * 16;       // k sub-offset (0 or 16)
    const float* Ag = g_f + (size_t)(bi * 128 + lm) * DD + lk;
    const float* Bg = g_f + (size_t)(bj * 128 + lm) * DD + lk;

    for (int kt = 0; kt < 8; ++kt) {
        #pragma unroll
        for (int q = 0; q < 4; ++q) {
            float4 va = *(const float4*)(Ag + kt * 32 + q * 4);
            As[lk + q * 4 + 0][lm] = va.x;
            As[lk + q * 4 + 1][lm] = va.y;
            As[lk + q * 4 + 2][lm] = va.z;
            As[lk + q * 4 + 3][lm] = va.w;
            float4 vb = *(const float4*)(Bg + kt * 32 + q * 4);
            Bs[lk + q * 4 + 0][lm] = vb.x;
            Bs[lk + q * 4 + 1][lm] = vb.y;
            Bs[lk + q * 4 + 2][lm] = vb.z;
            Bs[lk + q * 4 + 3][lm] = vb.w;
        }
        __syncthreads();
        #pragma unroll
        for (int k = 0; k < 32; ++k) {
            float a[8], b[8];
            *(float4*)(a)     = *(const float4*)&As[k][ty * 8];
            *(float4*)(a + 4) = *(const float4*)&As[k][ty * 8 + 4];
            *(float4*)(b)     = *(const float4*)&Bs[k][tx * 8];
            *(float4*)(b + 4) = *(const float4*)&Bs[k][tx * 8 + 4];
            #pragma unroll
            for (int i = 0; i < 8; i++)
                #pragma unroll
                for (int j = 0; j < 8; j++)
                    acc[i][j] = fmaf(a[i], b[j], acc[i][j]);
        }
        __syncthreads();
    }

    // ---- epilogue: dist + pass-1 mining ----
    __shared__ int      sLabR[128], sLabC[128];
    __shared__ float    sSqR[128],  sSqC[128];
    __shared__ unsigned sMinR[128], sMaxR[128], sMinC[128], sMaxC[128];

    if (tid < 128) {
        int r = bi * 128 + tid, c = bj * 128 + tid;
        sLabR[tid] = labels[r];  sLabC[tid] = labels[c];
        sSqR[tid]  = g_sq[r];    sSqC[tid]  = g_sq[c];
        sMinR[tid] = 0x7F800000u; sMaxR[tid] = 0u;
        sMinC[tid] = 0x7F800000u; sMaxC[tid] = 0u;
    }
    __syncthreads();

    #pragma unroll
    for (int i = 0; i < 8; i++) {
        int ri = ty * 8 + i;
        #pragma unroll
        for (int j = 0; j < 8; j++) {
            int rj = tx * 8 + j;
            float d2 = sSqR[ri] + sSqC[rj] - 2.0f * acc[i][j];
            float d = sqrtf(fmaxf(d2, 1e-12f));
            acc[i][j] = d;  // repurpose acc to hold dist
            unsigned db = __float_as_uint(d);
            if (sLabR[ri] == sLabC[rj]) {
                if (d < 0.99999f) {   // 1 - EPSILON
                    atomicMin(&sMinR[ri], db);
                    atomicMin(&sMinC[rj], db);
                }
            } else {
                atomicMax(&sMaxR[ri], db);
                atomicMax(&sMaxC[rj], db);
            }
        }
        // row-major store (coalesced float4)
        float* dst = g_dist + (size_t)(bi * 128 + ri) * BB + bj * 128 + tx * 8;
        *(float4*)dst       = make_float4(acc[i][0], acc[i][1], acc[i][2], acc[i][3]);
        *(float4*)(dst + 4) = make_float4(acc[i][4], acc[i][5], acc[i][6], acc[i][7]);
    }

    if (bi != bj) {
        // mirrored tile: g_dist[gj][gi]; per thread 32B contiguous per j
        #pragma unroll
        for (int j = 0; j < 8; j++) {
            int gj = bj * 128 + tx * 8 + j;
            float* dst = g_dist + (size_t)gj * BB + bi * 128 + ty * 8;
            *(float4*)dst       = make_float4(acc[0][j], acc[1][j], acc[2][j], acc[3][j]);
            *(float4*)(dst + 4) = make_float4(acc[4][j], acc[5][j], acc[6][j], acc[7][j]);
        }
    }

    __syncthreads();
    if (tid < 128) {
        atomicMin(&g_minpos[bi * 128 + tid], sMinR[tid]);
        atomicMax(&g_maxneg[bi * 128 + tid], sMaxR[tid]);
        if (bi != bj) {
            atomicMin(&g_minpos[bj * 128 + tid], sMinC[tid]);
            atomicMax(&g_maxneg[bj * 128 + tid], sMaxC[tid]);
        }
    }
}

// ---------------------------------------------------------------------------
// Kernel 3: pass 2 — per-row masked exp sums and final loss.
// one block (256 threads) per row
// ---------------------------------------------------------------------------
__global__ __launch_bounds__(256) void row_kernel(const int* __restrict__ labels,
                                                  float* __restrict__ out) {
    int i = blockIdx.x;
    int tid = threadIdx.x;
    int li = labels[i];
    float minpos = __uint_as_float(g_minpos[i]);
    float maxneg = __uint_as_float(g_maxneg[i]);

    float posSum = 0.0f, negSum = 0.0f;
    int pc = 0, nc = 0;

    const float4* drow = (const float4*)(g_dist + (size_t)i * BB);
    const int4*   lrow = (const int4*)labels;

    for (int jt = tid; jt < BB / 4; jt += 256) {
        float4 d4 = drow[jt];
        int4 l4 = lrow[jt];
        float dv[4] = {d4.x, d4.y, d4.z, d4.w};
        int lv[4] = {l4.x, l4.y, l4.z, l4.w};
        #pragma unroll
        for (int q = 0; q < 4; q++) {
            float d = dv[q];
            if (lv[q] == li) {
                if (d < 0.99999f && (d - 0.1f < maxneg)) {
                    pc++;
                    posSum += expf(2.0f * (d - 0.7f));   // SCALE_POS*(d + M_RANK - ALPHA)
                }
            } else {
                if (d + 0.1f > minpos) {
                    nc++;
                    negSum += expf(-40.0f * (d - 1.0f)); // -SCALE_NEG*(d - ALPHA)
                }
            }
        }
    }

    // block reduce
    #pragma unroll
    for (int o = 16; o > 0; o >>= 1) {
        posSum += __shfl_xor_sync(0xffffffffu, posSum, o);
        negSum += __shfl_xor_sync(0xffffffffu, negSum, o);
        pc     += __shfl_xor_sync(0xffffffffu, pc, o);
        nc     += __shfl_xor_sync(0xffffffffu, nc, o);
    }
    __shared__ float rp[8], rn[8];
    __shared__ int   cp[8], cn[8];
    if ((tid & 31) == 0) {
        rp[tid >> 5] = posSum; rn[tid >> 5] = negSum;
        cp[tid >> 5] = pc;     cn[tid >> 5] = nc;
    }
    __syncthreads();
    if (tid == 0) {
        float ps = 0.0f, ns = 0.0f; int p = 0, n = 0;
        #pragma unroll
        for (int w = 0; w < 8; w++) { ps += rp[w]; ns += rn[w]; p += cp[w]; n += cn[w]; }
        if (p >= 1 && n >= 1) {
            float loss = log1pf(ps) / ((float)p + 1e-5f) + log1pf(ns) * 0.025f;
            atomicAdd(out, loss * (1.0f / 8192.0f));
        }
    }
}

// ---------------------------------------------------------------------------
extern "C" void kernel_launch(void* const* d_in, const int* in_sizes, int n_in,
                              void* d_out, int out_size) {
    const float* feats = (const float*)d_in[0];
    const int* labels = (const int*)d_in[1];
    float* out = (float*)d_out;

    init_kernel<<<(BB + 255) / 256, 256>>>(out);
    norm_kernel<<<BB, 256>>>(feats);
    dim3 grid(BB / 128, BB / 128);
    gemm_kernel<<<grid, 256>>>(labels);
    row_kernel<<<BB, 256>>>(labels, out);
}

// round 2
// speedup vs baseline: 1.5985x; 1.5985x over previous
#include <cuda_runtime.h>
#include <math.h>

#define BB 8192
#define DD 256

// Scratch (device globals — no allocations allowed in kernel_launch)
__device__ float    g_f[BB * DD];                 // normalized feats
__device__ float    g_sq[BB];                     // per-row sum of squares of normalized feats
__device__ float    g_dist[(size_t)BB * BB];      // full distance matrix (256 MiB)
__device__ unsigned g_minpos[BB];                 // float bits, min over mined positives
__device__ unsigned g_maxneg[BB];                 // float bits, max over negatives

// ---------------------------------------------------------------------------
// Kernel 0: init accumulators
// ---------------------------------------------------------------------------
__global__ void init_kernel(float* out) {
    int t = blockIdx.x * blockDim.x + threadIdx.x;
    if (t < BB) {
        g_minpos[t] = 0x7F800000u;   // +inf
        g_maxneg[t] = 0u;            // 0.0f (all dists >= 0; rows w/o negs are invalid anyway)
    }
    if (t == 0) out[0] = 0.0f;
}

// ---------------------------------------------------------------------------
// Kernel 1: normalize rows; also compute sq = sum(fn*fn) per row
// one block (256 threads) per row
// ---------------------------------------------------------------------------
__global__ __launch_bounds__(256) void norm_kernel(const float* __restrict__ feats) {
    int row = blockIdx.x;
    int tid = threadIdx.x;
    float v = feats[row * DD + tid];

    float s = v * v;
    #pragma unroll
    for (int o = 16; o > 0; o >>= 1) s += __shfl_xor_sync(0xffffffffu, s, o);

    __shared__ float sw[8];
    if ((tid & 31) == 0) sw[tid >> 5] = s;
    __syncthreads();
    float tot = sw[0] + sw[1] + sw[2] + sw[3] + sw[4] + sw[5] + sw[6] + sw[7];

    float inv = 1.0f / (sqrtf(tot) + 1e-12f);
    float fn = v * inv;
    g_f[row * DD + tid] = fn;

    float s2 = fn * fn;
    #pragma unroll
    for (int o = 16; o > 0; o >>= 1) s2 += __shfl_xor_sync(0xffffffffu, s2, o);
    __syncthreads();
    if ((tid & 31) == 0) sw[tid >> 5] = s2;
    __syncthreads();
    if (tid == 0)
        g_sq[row] = sw[0] + sw[1] + sw[2] + sw[3] + sw[4] + sw[5] + sw[6] + sw[7];
}

// ---------------------------------------------------------------------------
// Kernel 2: tiled fp32 GEMM (dot products) + dist epilogue + pass-1 mining.
// 128x128 tile per 256-thread block, 8x8 per thread. Only bi <= bj computed;
// transposed tile is mirrored into g_dist. Per-row/col min/max done in shared
// memory, then folded into global via ~512 atomics per block.
// ---------------------------------------------------------------------------
__global__ __launch_bounds__(256) void gemm_kernel(const int* __restrict__ labels) {
    int bj = blockIdx.x;   // column tile
    int bi = blockIdx.y;   // row tile
    if (bi > bj) return;

    __shared__ float As[32][128];
    __shared__ float Bs[32][128];

    int tid = threadIdx.x;
    int tx = tid & 15;      // 0..15 -> 8 cols each
    int ty = tid >> 4;      // 0..15 -> 8 rows each

    float acc[8][8];
    #pragma unroll
    for (int i = 0; i < 8; i++)
        #pragma unroll
        for (int j = 0; j < 8; j++) acc[i][j] = 0.0f;

    int lm = tid >> 1;             // row within tile loaded by this thread (0..127)
    int lk = (tid & 1) * 16;       // k sub-offset (0 or 16)
    const float* Ag = g_f + (size_t)(bi * 128 + lm) * DD + lk;
    const float* Bg = g_f + (size_t)(bj * 128 + lm) * DD + lk;

    for (int kt = 0; kt < 8; ++kt) {
        #pragma unroll
        for (int q = 0; q < 4; ++q) {
            float4 va = *(const float4*)(Ag + kt * 32 + q * 4);
            As[lk + q * 4 + 0][lm] = va.x;
            As[lk + q * 4 + 1][lm] = va.y;
            As[lk + q * 4 + 2][lm] = va.z;
            As[lk + q * 4 + 3][lm] = va.w;
            float4 vb = *(const float4*)(Bg + kt * 32 + q * 4);
            Bs[lk + q * 4 + 0][lm] = vb.x;
            Bs[lk + q * 4 + 1][lm] = vb.y;
            Bs[lk + q * 4 + 2][lm] = vb.z;
            Bs[lk + q * 4 + 3][lm] = vb.w;
        }
        __syncthreads();
        #pragma unroll
        for (int k = 0; k < 32; ++k) {
            float a[8], b[8];
            *(float4*)(a)     = *(const float4*)&As[k][ty * 8];
            *(float4*)(a + 4) = *(const float4*)&As[k][ty * 8 + 4];
            *(float4*)(b)     = *(const float4*)&Bs[k][tx * 8];
            *(float4*)(b + 4) = *(const float4*)&Bs[k][tx * 8 + 4];
            #pragma unroll
            for (int i = 0; i < 8; i++)
                #pragma unroll
                for (int j = 0; j < 8; j++)
                    acc[i][j] = fmaf(a[i], b[j], acc[i][j]);
        }
        __syncthreads();
    }

    // ---- epilogue: dist + pass-1 mining ----
    __shared__ int      sLabR[128], sLabC[128];
    __shared__ float    sSqR[128],  sSqC[128];
    __shared__ unsigned sMinR[128], sMaxR[128], sMinC[128], sMaxC[128];

    if (tid < 128) {
        int r = bi * 128 + tid, c = bj * 128 + tid;
        sLabR[tid] = labels[r];  sLabC[tid] = labels[c];
        sSqR[tid]  = g_sq[r];    sSqC[tid]  = g_sq[c];
        sMinR[tid] = 0x7F800000u; sMaxR[tid] = 0u;
        sMinC[tid] = 0x7F800000u; sMaxC[tid] = 0u;
    }
    __syncthreads();

    #pragma unroll
    for (int i = 0; i < 8; i++) {
        int ri = ty * 8 + i;
        #pragma unroll
        for (int j = 0; j < 8; j++) {
            int rj = tx * 8 + j;
            float d2 = sSqR[ri] + sSqC[rj] - 2.0f * acc[i][j];
            float d = sqrtf(fmaxf(d2, 1e-12f));
            acc[i][j] = d;  // repurpose acc to hold dist
            unsigned db = __float_as_uint(d);
            if (sLabR[ri] == sLabC[rj]) {
                if (d < 0.99999f) {   // 1 - EPSILON
                    atomicMin(&sMinR[ri], db);
                    atomicMin(&sMinC[rj], db);
                }
            } else {
                atomicMax(&sMaxR[ri], db);
                atomicMax(&sMaxC[rj], db);
            }
        }
        // row-major store (coalesced float4)
        float* dst = g_dist + (size_t)(bi * 128 + ri) * BB + bj * 128 + tx * 8;
        *(float4*)dst       = make_float4(acc[i][0], acc[i][1], acc[i][2], acc[i][3]);
        *(float4*)(dst + 4) = make_float4(acc[i][4], acc[i][5], acc[i][6], acc[i][7]);
    }

    if (bi != bj) {
        // mirrored tile: g_dist[gj][gi]; per thread 32B contiguous per j
        #pragma unroll
        for (int j = 0; j < 8; j++) {
            int gj = bj * 128 + tx * 8 + j;
            float* dst = g_dist + (size_t)gj * BB + bi * 128 + ty * 8;
            *(float4*)dst       = make_float4(acc[0][j], acc[1][j], acc[2][j], acc[3][j]);
            *(float4*)(dst + 4) = make_float4(acc[4][j], acc[5][j], acc[6][j], acc[7][j]);
        }
    }

    __syncthreads();
    if (tid < 128) {
        atomicMin(&g_minpos[bi * 128 + tid], sMinR[tid]);
        atomicMax(&g_maxneg[bi * 128 + tid], sMaxR[tid]);
        if (bi != bj) {
            atomicMin(&g_minpos[bj * 128 + tid], sMinC[tid]);
            atomicMax(&g_maxneg[bj * 128 + tid], sMaxC[tid]);
        }
    }
}

// ---------------------------------------------------------------------------
// Kernel 3: pass 2 — per-row masked exp sums and final loss.
// one block (256 threads) per row
// ---------------------------------------------------------------------------
__global__ __launch_bounds__(256) void row_kernel(const int* __restrict__ labels,
                                                  float* __restrict__ out) {
    int i = blockIdx.x;
    int tid = threadIdx.x;
    int li = labels[i];
    float minpos = __uint_as_float(g_minpos[i]);
    float maxneg = __uint_as_float(g_maxneg[i]);

    float posSum = 0.0f, negSum = 0.0f;
    int pc = 0, nc = 0;

    const float4* drow = (const float4*)(g_dist + (size_t)i * BB);
    const int4*   lrow = (const int4*)labels;

    for (int jt = tid; jt < BB / 4; jt += 256) {
        float4 d4 = drow[jt];
        int4 l4 = lrow[jt];
        float dv[4] = {d4.x, d4.y, d4.z, d4.w};
        int lv[4] = {l4.x, l4.y, l4.z, l4.w};
        #pragma unroll
        for (int q = 0; q < 4; q++) {
            float d = dv[q];
            if (lv[q] == li) {
                if (d < 0.99999f && (d - 0.1f < maxneg)) {
                    pc++;
                    posSum += expf(2.0f * (d - 0.7f));   // SCALE_POS*(d + M_RANK - ALPHA)
                }
            } else {
                if (d + 0.1f > minpos) {
                    nc++;
                    negSum += expf(-40.0f * (d - 1.0f)); // -SCALE_NEG*(d - ALPHA)
                }
            }
        }
    }

    // block reduce
    #pragma unroll
    for (int o = 16; o > 0; o >>= 1) {
        posSum += __shfl_xor_sync(0xffffffffu, posSum, o);
        negSum += __shfl_xor_sync(0xffffffffu, negSum, o);
        pc     += __shfl_xor_sync(0xffffffffu, pc, o);
        nc     += __shfl_xor_sync(0xffffffffu, nc, o);
    }
    __shared__ float rp[8], rn[8];
    __shared__ int   cp[8], cn[8];
    if ((tid & 31) == 0) {
        rp[tid >> 5] = posSum; rn[tid >> 5] = negSum;
        cp[tid >> 5] = pc;     cn[tid >> 5] = nc;
    }
    __syncthreads();
    if (tid == 0) {
        float ps = 0.0f, ns = 0.0f; int p = 0, n = 0;
        #pragma unroll
        for (int w = 0; w < 8; w++) { ps += rp[w]; ns += rn[w]; p += cp[w]; n += cn[w]; }
        if (p >= 1 && n >= 1) {
            float loss = log1pf(ps) / ((float)p + 1e-5f) + log1pf(ns) * 0.025f;
            atomicAdd(out, loss * (1.0f / 8192.0f));
        }
    }
}

// ---------------------------------------------------------------------------
extern "C" void kernel_launch(void* const* d_in, const int* in_sizes, int n_in,
                              void* d_out, int out_size) {
    const float* feats = (const float*)d_in[0];
    const int* labels = (const int*)d_in[1];
    float* out = (float*)d_out;

    init_kernel<<<(BB + 255) / 256, 256>>>(out);
    norm_kernel<<<BB, 256>>>(feats);
    dim3 grid(BB / 128, BB / 128);
    gemm_kernel<<<grid, 256>>>(labels);
    row_kernel<<<BB, 256>>>(labels, out);
}

// round 4
// speedup vs baseline: 5.5733x; 3.4867x over previous
#include <cuda_runtime.h>
#include <cuda_bf16.h>
#include <math.h>
#include <stdint.h>

#define BB 8192
#define DD 256
#define NCLS 512
#define CAP (1u << 18)

// ---------------- device scratch ----------------
__device__ __nv_bfloat16 g_bf[BB * DD];     // normalized feats, bf16
__device__ float    g_sq[BB];               // per-row |f|^2 (fp32)
__device__ float    g_negsum[BB];
__device__ float    g_possum[BB];
__device__ int      g_pc[BB];
__device__ unsigned g_maxneg[BB];           // float bits
__device__ int      g_hist[NCLS];
__device__ unsigned g_ccnt;
__device__ int      g_crow[CAP];
__device__ float    g_cd[CAP];

// ---------------- helpers ----------------
__device__ __forceinline__ uint32_t smem_u32(const void* p) {
    uint32_t a;
    asm("{ .reg .u64 t; cvta.to.shared.u64 t, %1; cvt.u32.u64 %0, t; }" : "=r"(a) : "l"(p));
    return a;
}
__device__ __forceinline__ void cp_async16(uint32_t dst, const void* src) {
    asm volatile("cp.async.cg.shared.global [%0], [%1], 16;" :: "r"(dst), "l"(src));
}
#define CP_COMMIT() asm volatile("cp.async.commit_group;" ::: "memory")
template <int N> __device__ __forceinline__ void cp_wait() {
    asm volatile("cp.async.wait_group %0;" :: "n"(N) : "memory");
}
__device__ __forceinline__ void ldsm4(uint32_t& r0, uint32_t& r1, uint32_t& r2, uint32_t& r3,
                                      uint32_t a) {
    asm volatile("ldmatrix.sync.aligned.m8n8.x4.shared.b16 {%0,%1,%2,%3}, [%4];"
                 : "=r"(r0), "=r"(r1), "=r"(r2), "=r"(r3) : "r"(a));
}
__device__ __forceinline__ void mma16816(float* c, uint32_t a0, uint32_t a1, uint32_t a2,
                                         uint32_t a3, uint32_t b0, uint32_t b1) {
    asm volatile(
        "mma.sync.aligned.m16n8k16.row.col.f32.bf16.bf16.f32 "
        "{%0,%1,%2,%3},{%4,%5,%6,%7},{%8,%9},{%0,%1,%2,%3};"
        : "+f"(c[0]), "+f"(c[1]), "+f"(c[2]), "+f"(c[3])
        : "r"(a0), "r"(a1), "r"(a2), "r"(a3), "r"(b0), "r"(b1));
}

// ---------------- SMEM layout (dynamic) ----------------
// [0,65536): 2 buffers x (A 16K + B 16K), rows of 128B with 16B-unit xor swizzle
#define OFF_MISC 65536
#define SMEM_BYTES (OFF_MISC + 4096)

// ---------------------------------------------------------------------------
__global__ void init_kernel(float* out) {
    int t = blockIdx.x * blockDim.x + threadIdx.x;
    if (t < BB) {
        g_negsum[t] = 0.0f; g_possum[t] = 0.0f;
        g_pc[t] = 0;        g_maxneg[t] = 0u;
    }
    if (t < NCLS) g_hist[t] = 0;
    if (t == 0) { g_ccnt = 0u; out[0] = 0.0f; }
}

// ---------------------------------------------------------------------------
__global__ __launch_bounds__(256) void norm_kernel(const float* __restrict__ feats,
                                                   const int* __restrict__ labels) {
    int row = blockIdx.x;
    int tid = threadIdx.x;
    float v = feats[row * DD + tid];

    float s = v * v;
    #pragma unroll
    for (int o = 16; o > 0; o >>= 1) s += __shfl_xor_sync(0xffffffffu, s, o);
    __shared__ float sw[8];
    if ((tid & 31) == 0) sw[tid >> 5] = s;
    __syncthreads();
    float tot = sw[0] + sw[1] + sw[2] + sw[3] + sw[4] + sw[5] + sw[6] + sw[7];

    float inv = 1.0f / (sqrtf(tot) + 1e-12f);
    float fn = v * inv;
    g_bf[row * DD + tid] = __float2bfloat16(fn);

    float s2 = fn * fn;
    #pragma unroll
    for (int o = 16; o > 0; o >>= 1) s2 += __shfl_xor_sync(0xffffffffu, s2, o);
    __syncthreads();
    if ((tid & 31) == 0) sw[tid >> 5] = s2;
    __syncthreads();
    if (tid == 0) {
        g_sq[row] = sw[0] + sw[1] + sw[2] + sw[3] + sw[4] + sw[5] + sw[6] + sw[7];
        atomicAdd(&g_hist[labels[row]], 1);
    }
}

// ---------------------------------------------------------------------------
// Fused: bf16 HMMA Gram tile (128x128, bi<=bj) + dist + negSum + maxNeg +
// pos-candidate collection. No dist matrix ever hits DRAM.
// ---------------------------------------------------------------------------
__global__ __launch_bounds__(256) void gemm_ms(const int* __restrict__ labels) {
    int bj = blockIdx.x, bi = blockIdx.y;
    if (bi > bj) return;

    extern __shared__ char smem[];
    uint32_t sbase = smem_u32(smem);
    int tid = threadIdx.x;
    int lane = tid & 31, wid = tid >> 5;
    int wm = wid & 1, wn = wid >> 1;       // warp tile: 64(m) x 32(n)

    int*      sLabR = (int*)(smem + OFF_MISC);
    int*      sLabC = (int*)(smem + OFF_MISC + 512);
    float*    sSqR  = (float*)(smem + OFF_MISC + 1024);
    float*    sSqC  = (float*)(smem + OFF_MISC + 1536);
    float*    sNegR = (float*)(smem + OFF_MISC + 2048);
    float*    sNegC = (float*)(smem + OFF_MISC + 2560);
    unsigned* sMaxR = (unsigned*)(smem + OFF_MISC + 3072);
    unsigned* sMaxC = (unsigned*)(smem + OFF_MISC + 3584);

    if (tid < 128) {
        int r = bi * 128 + tid, c = bj * 128 + tid;
        sLabR[tid] = labels[r]; sLabC[tid] = labels[c];
        sSqR[tid] = g_sq[r];    sSqC[tid] = g_sq[c];
        sNegR[tid] = 0.0f;      sNegC[tid] = 0.0f;
        sMaxR[tid] = 0u;        sMaxC[tid] = 0u;
    }

    float acc[4][4][4] = {};

    auto load_chunk = [&](int c, int buf) {
        #pragma unroll
        for (int q = 0; q < 4; q++) {
            int idx = q * 256 + tid;
            int r = idx >> 3, u = idx & 7;
            uint32_t sw = (uint32_t)((u ^ (r & 7)) * 16);
            cp_async16(sbase + buf * 32768 + r * 128 + sw,
                       g_bf + (size_t)(bi * 128 + r) * DD + c * 64 + u * 8);
            cp_async16(sbase + buf * 32768 + 16384 + r * 128 + sw,
                       g_bf + (size_t)(bj * 128 + r) * DD + c * 64 + u * 8);
        }
        CP_COMMIT();
    };

    load_chunk(0, 0);

    for (int c = 0; c < 4; c++) {
        if (c + 1 < 4) { load_chunk(c + 1, (c + 1) & 1); cp_wait<1>(); }
        else           { cp_wait<0>(); }
        __syncthreads();

        uint32_t base = sbase + (c & 1) * 32768;
        #pragma unroll
        for (int ks = 0; ks < 4; ks++) {
            uint32_t a[4][4];
            #pragma unroll
            for (int mt = 0; mt < 4; mt++) {
                int rowA = wm * 64 + mt * 16 + (lane & 15);
                uint32_t unit = (uint32_t)(ks * 2 + (lane >> 4));
                ldsm4(a[mt][0], a[mt][1], a[mt][2], a[mt][3],
                      base + rowA * 128 + ((unit ^ (rowA & 7)) * 16));
            }
            uint32_t bb[2][4];
            #pragma unroll
            for (int tp = 0; tp < 2; tp++) {
                int nrow = wn * 32 + tp * 16 + (lane & 7) + ((lane >> 4) * 8);
                uint32_t unit = (uint32_t)(ks * 2 + ((lane >> 3) & 1));
                ldsm4(bb[tp][0], bb[tp][1], bb[tp][2], bb[tp][3],
                      base + 16384 + nrow * 128 + ((unit ^ (nrow & 7)) * 16));
            }
            #pragma unroll
            for (int mt = 0; mt < 4; mt++)
                #pragma unroll
                for (int nt = 0; nt < 4; nt++)
                    mma16816(acc[mt][nt],
                             a[mt][0], a[mt][1], a[mt][2], a[mt][3],
                             bb[nt >> 1][(nt & 1) * 2], bb[nt >> 1][(nt & 1) * 2 + 1]);
        }
        __syncthreads();
    }

    // ---- epilogue ----
    int g = lane >> 2, tg = lane & 3;
    float    colNeg[8];
    unsigned colMax[8];
    #pragma unroll
    for (int x = 0; x < 8; x++) { colNeg[x] = 0.0f; colMax[x] = 0u; }

    #pragma unroll
    for (int mt = 0; mt < 4; mt++) {
        #pragma unroll
        for (int rh = 0; rh < 2; rh++) {
            int row = wm * 64 + mt * 16 + g + rh * 8;
            int gi = bi * 128 + row;
            int labRv = sLabR[row];
            float sqRv = sSqR[row];
            float rne = 0.0f, rmx = 0.0f;
            #pragma unroll
            for (int nt = 0; nt < 4; nt++) {
                #pragma unroll
                for (int p = 0; p < 2; p++) {
                    int col = wn * 32 + nt * 8 + tg * 2 + p;
                    float dot = acc[mt][nt][rh * 2 + p];
                    float d2 = sqRv + sSqC[col] - 2.0f * dot;
                    float d = sqrtf(fmaxf(d2, 1e-12f));
                    int gj = bj * 128 + col;
                    if (gi == gj) d = 1e-6f;      // exact diagonal (matches ref clamp)
                    if (labRv == sLabC[col]) {
                        if (d < 0.99999f) {        // pos candidate — rare
                            unsigned ix = atomicAdd(&g_ccnt, 1u);
                            if (ix < CAP) { g_crow[ix] = gi; g_cd[ix] = d; }
                            if (bi != bj) {
                                unsigned iy = atomicAdd(&g_ccnt, 1u);
                                if (iy < CAP) { g_crow[iy] = gj; g_cd[iy] = d; }
                            }
                        }
                    } else {
                        float e = __expf(-40.0f * (d - 1.0f));
                        rne += e;
                        colNeg[nt * 2 + p] += e;
                        rmx = fmaxf(rmx, d);
                        unsigned db = __float_as_uint(d);
                        if (db > colMax[nt * 2 + p]) colMax[nt * 2 + p] = db;
                    }
                }
            }
            if (rne != 0.0f) atomicAdd(&sNegR[row], rne);
            if (rmx > 0.0f) atomicMax(&sMaxR[row], __float_as_uint(rmx));
        }
    }

    if (bi != bj) {
        #pragma unroll
        for (int x = 0; x < 8; x++) {
            int col = wn * 32 + (x >> 1) * 8 + tg * 2 + (x & 1);
            if (colNeg[x] != 0.0f) atomicAdd(&sNegC[col], colNeg[x]);
            if (colMax[x]) atomicMax(&sMaxC[col], colMax[x]);
        }
    }
    __syncthreads();

    if (tid < 128) {
        float v = sNegR[tid];
        if (v != 0.0f) atomicAdd(&g_negsum[bi * 128 + tid], v);
        unsigned m = sMaxR[tid];
        if (m) atomicMax(&g_maxneg[bi * 128 + tid], m);
        if (bi != bj) {
            float w = sNegC[tid];
            if (w != 0.0f) atomicAdd(&g_negsum[bj * 128 + tid], w);
            unsigned n2 = sMaxC[tid];
            if (n2) atomicMax(&g_maxneg[bj * 128 + tid], n2);
        }
    }
}

// ---------------------------------------------------------------------------
// resolve pos candidates against completed max_neg
// ---------------------------------------------------------------------------
__global__ void resolve_kernel() {
    unsigned t = blockIdx.x * blockDim.x + threadIdx.x;
    unsigned cnt = g_ccnt;
    if (cnt > CAP) cnt = CAP;
    if (t >= cnt) return;
    int row = g_crow[t];
    float d = g_cd[t];
    float mx = __uint_as_float(g_maxneg[row]);
    if (d - 0.1f < mx) {
        atomicAdd(&g_possum[row], __expf(2.0f * (d - 0.7f)));
        atomicAdd(&g_pc[row], 1);
    }
}

// ---------------------------------------------------------------------------
__global__ void final_kernel(const int* __restrict__ labels, float* __restrict__ out) {
    int i = blockIdx.x * blockDim.x + threadIdx.x;
    if (i >= BB) return;
    int nc = BB - g_hist[labels[i]];
    int pc = g_pc[i];
    if (pc >= 1 && nc >= 1) {
        float loss = log1pf(g_possum[i]) / ((float)pc + 1e-5f)
                   + log1pf(g_negsum[i]) * 0.025f;
        atomicAdd(out, loss * (1.0f / BB));
    }
}

// ---------------------------------------------------------------------------
extern "C" void kernel_launch(void* const* d_in, const int* in_sizes, int n_in,
                              void* d_out, int out_size) {
    const float* feats = (const float*)d_in[0];
    const int* labels = (const int*)d_in[1];
    float* out = (float*)d_out;

    static bool attr_set = false;
    if (!attr_set) {
        cudaFuncSetAttribute(gemm_ms, cudaFuncAttributeMaxDynamicSharedMemorySize, SMEM_BYTES);
        attr_set = true;
    }

    init_kernel<<<BB / 256, 256>>>(out);
    norm_kernel<<<BB, 256>>>(feats, labels);
    dim3 grid(BB / 128, BB / 128);
    gemm_ms<<<grid, 256, SMEM_BYTES>>>(labels);
    resolve_kernel<<<CAP / 256, 256>>>();
    final_kernel<<<BB / 256, 256>>>(labels, out);
}